// round 1
// baseline (speedup 1.0000x reference)
#include <cuda_runtime.h>
#include <cstdint>
#include <math.h>

#define BB   4096
#define SS   50
#define HIDD 256
#define NHH  4
#define HDD  64
#define FBB  26
#define PPER 208   // NH*FB*2

typedef unsigned long long u64;

// ---------------- scratch (device globals; no allocation allowed) ----------------
__device__ __align__(16) float g_ctx[BB * HIDD];
__device__ __align__(16) float g_h[BB * HIDD];
__device__ __align__(16) float g_fb[BB * PPER];

// ---------------- packed f32x2 helpers ----------------
__device__ __forceinline__ void ffma2(u64 &d, u64 a, u64 b) {
    asm("fma.rn.f32x2 %0, %1, %2, %0;" : "+l"(d) : "l"(a), "l"(b));
}
__device__ __forceinline__ u64 pack2(float lo, float hi) {
    u64 r; asm("mov.b64 %0, {%1, %2};" : "=l"(r) : "f"(lo), "f"(hi)); return r;
}
__device__ __forceinline__ void unpack2(u64 v, float &lo, float &hi) {
    asm("mov.b64 {%0, %1}, %2;" : "=f"(lo), "=f"(hi) : "l"(v));
}

// ---------------- K1: attr_ctx = mean over S ----------------
__global__ void k_ctx(const float* __restrict__ attr) {
    int idx = blockIdx.x * blockDim.x + threadIdx.x;      // one float4 per thread
    if (idx >= BB * (HIDD / 4)) return;
    int b  = idx >> 6;
    int c4 = idx & 63;
    const float4* p = reinterpret_cast<const float4*>(attr + (size_t)b * SS * HIDD) + c4;
    float sx = 0.f, sy = 0.f, sz = 0.f, sw = 0.f;
    #pragma unroll
    for (int t = 0; t < SS; t++) {
        float4 v = p[(size_t)t * (HIDD / 4)];
        sx += v.x; sy += v.y; sz += v.z; sw += v.w;
    }
    float4 o; o.x = sx * 0.02f; o.y = sy * 0.02f; o.z = sz * 0.02f; o.w = sw * 0.02f;
    reinterpret_cast<float4*>(g_ctx)[idx] = o;
}

// ---------------- K2: h = gelu(ctx @ w1 + b1)  (exact gelu) ----------------
__global__ __launch_bounds__(256) void k_mlp1(const float* __restrict__ w1,
                                              const float* __restrict__ b1) {
    __shared__ float cs[16 * HIDD];
    int b0  = blockIdx.x * 16;
    int tid = threadIdx.x;
    for (int i = tid; i < 16 * HIDD; i += 256) cs[i] = g_ctx[b0 * HIDD + i];
    __syncthreads();

    float acc[16];
    float bv = b1[tid];
    #pragma unroll
    for (int m = 0; m < 16; m++) acc[m] = bv;

    for (int k4 = 0; k4 < HIDD / 4; k4++) {
        int k = 4 * k4;
        float wa = w1[(k + 0) * HIDD + tid];
        float wb = w1[(k + 1) * HIDD + tid];
        float wc = w1[(k + 2) * HIDD + tid];
        float wd = w1[(k + 3) * HIDD + tid];
        #pragma unroll
        for (int m = 0; m < 16; m++) {
            float4 c4 = *reinterpret_cast<const float4*>(&cs[m * HIDD + k]);
            acc[m] += c4.x * wa + c4.y * wb + c4.z * wc + c4.w * wd;
        }
    }
    #pragma unroll
    for (int m = 0; m < 16; m++) {
        float x = acc[m];
        float g = 0.5f * x * (1.0f + erff(x * 0.70710678118654752f));
        g_h[(b0 + m) * HIDD + tid] = g;
    }
}

// ---------------- K3: adapt = h @ w2 + b2 ; fold base_filter/base_bias ----------------
__global__ __launch_bounds__(256) void k_mlp2(const float* __restrict__ w2,
                                              const float* __restrict__ b2,
                                              const float* __restrict__ bfil,
                                              const float* __restrict__ bbia) {
    __shared__ float hs[16 * HIDD];
    int b0  = blockIdx.x * 16;
    int tid = threadIdx.x;
    for (int i = tid; i < 16 * HIDD; i += 256) hs[i] = g_h[b0 * HIDD + i];
    __syncthreads();
    if (tid >= PPER) return;

    float acc[16];
    float bv = b2[tid];
    #pragma unroll
    for (int m = 0; m < 16; m++) acc[m] = bv;

    for (int k4 = 0; k4 < HIDD / 4; k4++) {
        int k = 4 * k4;
        float wa = w2[(k + 0) * PPER + tid];
        float wb = w2[(k + 1) * PPER + tid];
        float wc = w2[(k + 2) * PPER + tid];
        float wd = w2[(k + 3) * PPER + tid];
        #pragma unroll
        for (int m = 0; m < 16; m++) {
            float4 h4 = *reinterpret_cast<const float4*>(&hs[m * HIDD + k]);
            acc[m] += h4.x * wa + h4.y * wb + h4.z * wc + h4.w * wd;
        }
    }

    int h = tid / 52;
    int r = tid % 52;
    int fi = r >> 1;
    bool isScale = (r & 1) == 0;
    float basef = bfil[h * FBB + fi];
    float baseb = bbia[h * FBB + fi];
    #pragma unroll
    for (int m = 0; m < 16; m++) {
        float v = isScale ? basef * (1.0f + acc[m]) : (baseb + acc[m]);
        g_fb[(b0 + m) * PPER + tid] = v;
    }
}

// ---------------- K4: circulant conv + wavelet + combine + residual + LayerNorm ----
// one block per batch, 256 threads
// smem float offsets:
//   xs    0      : 12800  (50 x 256 item tile, later overwritten with res)
//   cws   12800  : 6400   (25 x 256 complex_weight reordered)
//   cd    19200  : 800    (4 heads x 100 duplicated float2 circulant coeffs)
//   bvs   20000  : 200    (4 heads x 50 bias vectors)
//   fbs   20200  : 208    (per-batch filter/bias params)
//   ctab  20408  : 50     (cos(2*pi*t/50))
//   gs    20458  : 256
//   bsv   20714  : 256
//   total 20970 floats = 83880 bytes
#define SMEM_FLOATS 20970

__global__ __launch_bounds__(256, 2) void k_main(const float* __restrict__ item,
                                                 const float* __restrict__ cw,
                                                 const float* __restrict__ gamma,
                                                 const float* __restrict__ beta,
                                                 float* __restrict__ out) {
    extern __shared__ float sm[];
    float* xs   = sm;
    float* cws  = sm + 12800;
    float* cd   = sm + 19200;
    float* bvs  = sm + 20000;
    float* fbs  = sm + 20200;
    float* ctab = sm + 20408;
    float* gs   = sm + 20458;
    float* bsv  = sm + 20714;

    int b   = blockIdx.x;
    int tid = threadIdx.x;
    const float* itemb = item + (size_t)b * SS * HIDD;

    // ---- stage loads ----
    for (int i = tid; i < SS * HIDD / 4; i += 256)
        reinterpret_cast<float4*>(xs)[i] = reinterpret_cast<const float4*>(itemb)[i];
    for (int i = tid; i < (SS / 2) * HIDD; i += 256) {
        int j = i >> 8, d = i & 255, h = d >> 6, dl = d & 63;
        cws[i] = cw[h * (25 * HDD) + j * HDD + dl];
    }
    if (tid < PPER) fbs[tid] = g_fb[b * PPER + tid];
    if (tid < 50)   ctab[tid] = cospif((float)tid * (1.0f / 25.0f)); // cos(2*pi*t/50)
    gs[tid]  = gamma[tid];
    bsv[tid] = beta[tid];
    __syncthreads();

    // ---- per-(head,m) circulant coeffs and bias vectors ----
    if (tid < 200) {
        int h = tid / 50, m = tid % 50;
        const float* fh = fbs + h * 52;
        float cacc = 0.f, bacc = 0.f;
        int idx = 0;
        #pragma unroll
        for (int k = 0; k < 26; k++) {
            float w  = (k == 0 || k == 25) ? 1.0f : 2.0f;
            float co = w * ctab[idx];
            cacc += fh[2 * k]     * co;
            bacc += fh[2 * k + 1] * co;
            idx += m; if (idx >= 50) idx -= 50;
        }
        cacc *= 0.02f;                       // 1/50
        bacc *= 0.14142135623730951f;        // 1/sqrt(50)
        float2 cc = make_float2(cacc, cacc); // duplicated for f32x2
        reinterpret_cast<float2*>(cd)[h * 100 + m]      = cc;
        reinterpret_cast<float2*>(cd)[h * 100 + m + 50] = cc;
        bvs[h * 50 + m] = bacc;
    }
    __syncthreads();

    // ---- circular convolution: thread = (parity p, column-pair dp) ----
    int p  = tid >> 7;
    int dp = tid & 127;
    int d0 = dp * 2;
    int h  = dp >> 5;

    u64 acc[25];
    #pragma unroll
    for (int i = 0; i < 25; i++) {
        float bv = bvs[h * 50 + 2 * i + p];
        acc[i] = pack2(bv, bv);
    }
    const u64* crow = reinterpret_cast<const u64*>(cd) + h * 100;
    for (int s = 0; s < SS; s++) {
        u64 xv = *reinterpret_cast<const u64*>(&xs[s * HIDD + d0]);
        const u64* cb = crow + (p - s + 50);   // index in [1,51]; +2*i stays < 100
        #pragma unroll
        for (int i = 0; i < 25; i++) ffma2(acc[i], xv, cb[2 * i]);
    }

    // ---- wavelet + combine + residual (read xs fully before overwrite) ----
    float sgn = p ? -1.0f : 1.0f;
    #pragma unroll
    for (int i = 0; i < 25; i++) {
        float2 e = *reinterpret_cast<const float2*>(&xs[(2 * i)     * HIDD + d0]);
        float2 o = *reinterpret_cast<const float2*>(&xs[(2 * i + 1) * HIDD + d0]);
        float2 w = *reinterpret_cast<const float2*>(&cws[i * HIDD + d0]);
        float ax = 0.5f * (e.x + o.x), ay = 0.5f * (e.y + o.y);
        float dx = 0.5f * (e.x - o.x) * w.x, dy = 0.5f * (e.y - o.y) * w.y;
        float wx = ax + sgn * dx, wy = ay + sgn * dy;
        float ix = p ? o.x : e.x;
        float iy = p ? o.y : e.y;
        float fx, fy; unpack2(acc[i], fx, fy);
        acc[i] = pack2(0.7f * wx + 0.3f * fx + ix,
                       0.7f * wy + 0.3f * fy + iy);
    }
    __syncthreads();
    #pragma unroll
    for (int i = 0; i < 25; i++)
        *reinterpret_cast<u64*>(&xs[(2 * i + p) * HIDD + d0]) = acc[i];
    __syncthreads();

    // ---- LayerNorm over HID, rows distributed over warps ----
    int wid = tid >> 5, lane = tid & 31;
    float* outb = out + (size_t)b * SS * HIDD;
    for (int t = wid; t < SS; t += 8) {
        float v[8];
        float s1 = 0.f, s2 = 0.f;
        #pragma unroll
        for (int q = 0; q < 8; q++) {
            v[q] = xs[t * HIDD + lane + 32 * q];
            s1 += v[q]; s2 += v[q] * v[q];
        }
        #pragma unroll
        for (int off = 16; off; off >>= 1) {
            s1 += __shfl_xor_sync(0xffffffffu, s1, off);
            s2 += __shfl_xor_sync(0xffffffffu, s2, off);
        }
        float mu  = s1 * (1.0f / 256.0f);
        float var = s2 * (1.0f / 256.0f) - mu * mu;
        float rs  = rsqrtf(var + 1e-12f);
        #pragma unroll
        for (int q = 0; q < 8; q++) {
            int c = lane + 32 * q;
            outb[t * HIDD + c] = (v[q] - mu) * rs * gs[c] + bsv[c];
        }
    }
}

// ---------------- launcher ----------------
extern "C" void kernel_launch(void* const* d_in, const int* in_sizes, int n_in,
                              void* d_out, int out_size) {
    const float* item = (const float*)d_in[0];
    const float* attr = (const float*)d_in[1];
    const float* cw   = (const float*)d_in[2];
    const float* bfil = (const float*)d_in[3];
    const float* bbia = (const float*)d_in[4];
    const float* w1   = (const float*)d_in[5];
    const float* b1   = (const float*)d_in[6];
    const float* w2   = (const float*)d_in[7];
    const float* b2   = (const float*)d_in[8];
    const float* gam  = (const float*)d_in[9];
    const float* bet  = (const float*)d_in[10];
    float* out = (float*)d_out;

    cudaFuncSetAttribute(k_main, cudaFuncAttributeMaxDynamicSharedMemorySize,
                         SMEM_FLOATS * (int)sizeof(float));

    k_ctx<<<(BB * (HIDD / 4) + 255) / 256, 256>>>(attr);
    k_mlp1<<<BB / 16, 256>>>(w1, b1);
    k_mlp2<<<BB / 16, 256>>>(w2, b2, bfil, bbia);
    k_main<<<BB, 256, SMEM_FLOATS * (int)sizeof(float)>>>(item, cw, gam, bet, out);
}

// round 2
// speedup vs baseline: 1.3192x; 1.3192x over previous
#include <cuda_runtime.h>
#include <cstdint>
#include <math.h>

#define BB   4096
#define SS   50
#define HIDD 256
#define NHH  4
#define HDD  64
#define FBB  26
#define PPER 208   // NH*FB*2

typedef unsigned long long u64;

// ---------------- scratch (device globals; no allocation allowed) ----------------
__device__ __align__(16) float g_fb[BB * PPER];

// ---------------- packed f32x2 helpers ----------------
__device__ __forceinline__ void ffma2(u64 &d, u64 a, u64 b) {
    asm("fma.rn.f32x2 %0, %1, %2, %0;" : "+l"(d) : "l"(a), "l"(b));
}
__device__ __forceinline__ u64 pack2(float lo, float hi) {
    u64 r; asm("mov.b64 %0, {%1, %2};" : "=l"(r) : "f"(lo), "f"(hi)); return r;
}
__device__ __forceinline__ void unpack2(u64 v, float &lo, float &hi) {
    asm("mov.b64 {%0, %1}, %2;" : "=f"(lo), "=f"(hi) : "l"(v));
}

// ---------------- fused prologue: ctx mean -> gelu MLP -> adapt + fold ----------
// grid = BB/8 = 512 blocks, 256 threads, 8 batches per block
__global__ __launch_bounds__(256) void k_pre(const float* __restrict__ attr,
                                             const float* __restrict__ w1,
                                             const float* __restrict__ b1,
                                             const float* __restrict__ w2,
                                             const float* __restrict__ b2,
                                             const float* __restrict__ bfil,
                                             const float* __restrict__ bbia) {
    __shared__ float cs[8 * HIDD];
    __shared__ float hs[8 * HIDD];
    int b0  = blockIdx.x * 8;
    int tid = threadIdx.x;

    // ---- phase A: ctx = mean over S ----
    {
        int c4 = tid & 63;     // float4 column
        int mg = tid >> 6;     // 0..3
        #pragma unroll
        for (int mo = 0; mo < 2; mo++) {
            int m = mg + mo * 4;
            const float4* p = reinterpret_cast<const float4*>(
                attr + (size_t)(b0 + m) * SS * HIDD) + c4;
            float sx = 0.f, sy = 0.f, sz = 0.f, sw = 0.f;
            #pragma unroll
            for (int t = 0; t < SS; t++) {
                float4 v = p[(size_t)t * (HIDD / 4)];
                sx += v.x; sy += v.y; sz += v.z; sw += v.w;
            }
            float4 o; o.x = sx * 0.02f; o.y = sy * 0.02f; o.z = sz * 0.02f; o.w = sw * 0.02f;
            reinterpret_cast<float4*>(cs)[m * (HIDD / 4) + c4] = o;
        }
    }
    __syncthreads();

    // ---- phase B: h = gelu(ctx @ w1 + b1) ----
    {
        float acc[8];
        float bv = b1[tid];
        #pragma unroll
        for (int m = 0; m < 8; m++) acc[m] = bv;
        for (int k4 = 0; k4 < HIDD / 4; k4++) {
            int k = 4 * k4;
            float wa = w1[(k + 0) * HIDD + tid];
            float wb = w1[(k + 1) * HIDD + tid];
            float wc = w1[(k + 2) * HIDD + tid];
            float wd = w1[(k + 3) * HIDD + tid];
            #pragma unroll
            for (int m = 0; m < 8; m++) {
                float4 c4 = *reinterpret_cast<const float4*>(&cs[m * HIDD + k]);
                acc[m] += c4.x * wa + c4.y * wb + c4.z * wc + c4.w * wd;
            }
        }
        #pragma unroll
        for (int m = 0; m < 8; m++) {
            float x = acc[m];
            hs[m * HIDD + tid] = 0.5f * x * (1.0f + erff(x * 0.70710678118654752f));
        }
    }
    __syncthreads();

    // ---- phase C: adapt = h @ w2 + b2, fold base filter/bias ----
    if (tid < PPER) {
        float acc[8];
        float bv = b2[tid];
        #pragma unroll
        for (int m = 0; m < 8; m++) acc[m] = bv;
        for (int k4 = 0; k4 < HIDD / 4; k4++) {
            int k = 4 * k4;
            float wa = w2[(k + 0) * PPER + tid];
            float wb = w2[(k + 1) * PPER + tid];
            float wc = w2[(k + 2) * PPER + tid];
            float wd = w2[(k + 3) * PPER + tid];
            #pragma unroll
            for (int m = 0; m < 8; m++) {
                float4 h4 = *reinterpret_cast<const float4*>(&hs[m * HIDD + k]);
                acc[m] += h4.x * wa + h4.y * wb + h4.z * wc + h4.w * wd;
            }
        }
        int h = tid / 52;
        int r = tid % 52;
        int fi = r >> 1;
        bool isScale = (r & 1) == 0;
        float basef = bfil[h * FBB + fi];
        float baseb = bbia[h * FBB + fi];
        #pragma unroll
        for (int m = 0; m < 8; m++) {
            float v = isScale ? basef * (1.0f + acc[m]) : (baseb + acc[m]);
            g_fb[(b0 + m) * PPER + tid] = v;
        }
    }
}

// ---------------- K4: circulant conv + wavelet + combine + residual + LayerNorm ----
// smem float offsets:
//   xs    0      : 12800  (50 x 256 item tile, later overwritten with res)
//   cws   12800  : 6400   (25 x 256 complex_weight reordered)
//   cd    19200  : 208    (4 heads x 26 duplicated float2 circulant coeffs, symmetric)
//   bvs   19408  : 200    (4 heads x 50 bias vectors)
//   fbs   19608  : 208    (per-batch filter/bias params)
//   ctab  19816  : 50     (cos(2*pi*t/50))
//   gs    19866  : 256
//   bsv   20122  : 256
//   total 20378 floats = 81512 bytes
#define SMEM_FLOATS 20378

__global__ __launch_bounds__(256, 2) void k_main(const float* __restrict__ item,
                                                 const float* __restrict__ cw,
                                                 const float* __restrict__ gamma,
                                                 const float* __restrict__ beta,
                                                 float* __restrict__ out) {
    extern __shared__ float sm[];
    float* xs   = sm;
    float* cws  = sm + 12800;
    float* cd   = sm + 19200;
    float* bvs  = sm + 19408;
    float* fbs  = sm + 19608;
    float* ctab = sm + 19816;
    float* gs   = sm + 19866;
    float* bsv  = sm + 20122;

    int b   = blockIdx.x;
    int tid = threadIdx.x;
    const float* itemb = item + (size_t)b * SS * HIDD;

    // ---- stage loads ----
    for (int i = tid; i < SS * HIDD / 4; i += 256)
        reinterpret_cast<float4*>(xs)[i] = reinterpret_cast<const float4*>(itemb)[i];
    for (int i = tid; i < (SS / 2) * HIDD; i += 256) {
        int j = i >> 8, d = i & 255, h = d >> 6, dl = d & 63;
        cws[i] = cw[h * (25 * HDD) + j * HDD + dl];
    }
    if (tid < PPER) fbs[tid] = g_fb[b * PPER + tid];
    if (tid < 50)   ctab[tid] = cospif((float)tid * (1.0f / 25.0f)); // cos(2*pi*t/50)
    gs[tid]  = gamma[tid];
    bsv[tid] = beta[tid];
    __syncthreads();

    // ---- circulant coeffs (even-symmetric: only m=0..25) + bias vectors ----
    if (tid < 104) {       // 4 heads x 26 coeffs
        int h = tid / 26, m = tid % 26;
        const float* fh = fbs + h * 52;
        float cacc = 0.f;
        int idx = 0;
        #pragma unroll
        for (int k = 0; k < 26; k++) {
            float w  = (k == 0 || k == 25) ? 1.0f : 2.0f;
            cacc += fh[2 * k] * w * ctab[idx];
            idx += m; if (idx >= 50) idx -= 50;
        }
        cacc *= 0.02f;                        // 1/50
        reinterpret_cast<float2*>(cd)[h * 26 + m] = make_float2(cacc, cacc);
    }
    if (tid < 200) {       // 4 heads x 50 bias values
        int h = tid / 50, m = tid % 50;
        const float* fh = fbs + h * 52;
        float bacc = 0.f;
        int idx = 0;
        #pragma unroll
        for (int k = 0; k < 26; k++) {
            float w  = (k == 0 || k == 25) ? 1.0f : 2.0f;
            bacc += fh[2 * k + 1] * w * ctab[idx];
            idx += m; if (idx >= 50) idx -= 50;
        }
        bvs[h * 50 + m] = bacc * 0.14142135623730951f;   // 1/sqrt(50)
    }
    __syncthreads();

    // ---- circular convolution: thread = (parity p, column-pair dp) ----
    // acc[i] holds row t = 2i+p. s-loop re-indexed: s = (sp + p) mod 50 so the
    // coefficient index (t - s) mod 50 = (2i - sp) mod 50 is COMPILE-TIME static.
    // Kernel is even-symmetric: c[d] = c[50-d], only 26 values; sp-parity split
    // means each half-pass touches only 13 coeff registers.
    int p  = tid >> 7;
    int dp = tid & 127;
    int d0 = dp * 2;
    int h  = dp >> 5;

    u64 acc[25];
    #pragma unroll
    for (int i = 0; i < 25; i++) {
        float bv = bvs[h * 50 + 2 * i + p];
        acc[i] = pack2(bv, bv);
    }

    const u64* cdh  = reinterpret_cast<const u64*>(cd) + h * 26;
    const float* xcol = xs + d0;

    // even-sp pass (sp = 0,2,...,48; srow = sp+p <= 49, no wrap)
    {
        u64 ce[13];
        #pragma unroll
        for (int j = 0; j < 13; j++) ce[j] = cdh[2 * j];
        #pragma unroll
        for (int e = 0; e < 25; e++) {
            const int sp = 2 * e;
            int srow = sp + p;
            u64 xv = *reinterpret_cast<const u64*>(xcol + srow * HIDD);
            #pragma unroll
            for (int i = 0; i < 25; i++) {
                const int dd = ((2 * i - sp) % 50 + 50) % 50;
                const int f  = (dd <= 25) ? dd : (50 - dd);   // even
                ffma2(acc[i], xv, ce[f >> 1]);
            }
        }
    }
    // odd-sp pass (sp = 1,3,...,49; srow wraps only at sp=49,p=1)
    {
        u64 co[13];
        #pragma unroll
        for (int j = 0; j < 13; j++) co[j] = cdh[2 * j + 1];
        #pragma unroll
        for (int o = 0; o < 25; o++) {
            const int sp = 2 * o + 1;
            int srow = sp + p;
            if (srow >= 50) srow -= 50;
            u64 xv = *reinterpret_cast<const u64*>(xcol + srow * HIDD);
            #pragma unroll
            for (int i = 0; i < 25; i++) {
                const int dd = ((2 * i - sp) % 50 + 50) % 50;
                const int f  = (dd <= 25) ? dd : (50 - dd);   // odd
                ffma2(acc[i], xv, co[(f - 1) >> 1]);
            }
        }
    }

    // ---- wavelet + combine + residual (read xs fully before overwrite) ----
    float sgn = p ? -1.0f : 1.0f;
    #pragma unroll
    for (int i = 0; i < 25; i++) {
        float2 e = *reinterpret_cast<const float2*>(&xs[(2 * i)     * HIDD + d0]);
        float2 o = *reinterpret_cast<const float2*>(&xs[(2 * i + 1) * HIDD + d0]);
        float2 w = *reinterpret_cast<const float2*>(&cws[i * HIDD + d0]);
        float ax = 0.5f * (e.x + o.x), ay = 0.5f * (e.y + o.y);
        float dx = 0.5f * (e.x - o.x) * w.x, dy = 0.5f * (e.y - o.y) * w.y;
        float wx = ax + sgn * dx, wy = ay + sgn * dy;
        float ix = p ? o.x : e.x;
        float iy = p ? o.y : e.y;
        float fx, fy; unpack2(acc[i], fx, fy);
        acc[i] = pack2(0.7f * wx + 0.3f * fx + ix,
                       0.7f * wy + 0.3f * fy + iy);
    }
    __syncthreads();
    #pragma unroll
    for (int i = 0; i < 25; i++)
        *reinterpret_cast<u64*>(&xs[(2 * i + p) * HIDD + d0]) = acc[i];
    __syncthreads();

    // ---- LayerNorm over HID, rows distributed over warps ----
    int wid = tid >> 5, lane = tid & 31;
    float* outb = out + (size_t)b * SS * HIDD;
    for (int t = wid; t < SS; t += 8) {
        float v[8];
        float s1 = 0.f, s2 = 0.f;
        #pragma unroll
        for (int q = 0; q < 8; q++) {
            v[q] = xs[t * HIDD + lane + 32 * q];
            s1 += v[q]; s2 += v[q] * v[q];
        }
        #pragma unroll
        for (int off = 16; off; off >>= 1) {
            s1 += __shfl_xor_sync(0xffffffffu, s1, off);
            s2 += __shfl_xor_sync(0xffffffffu, s2, off);
        }
        float mu  = s1 * (1.0f / 256.0f);
        float var = s2 * (1.0f / 256.0f) - mu * mu;
        float rs  = rsqrtf(var + 1e-12f);
        #pragma unroll
        for (int q = 0; q < 8; q++) {
            int c = lane + 32 * q;
            outb[t * HIDD + c] = (v[q] - mu) * rs * gs[c] + bsv[c];
        }
    }
}

// ---------------- launcher ----------------
extern "C" void kernel_launch(void* const* d_in, const int* in_sizes, int n_in,
                              void* d_out, int out_size) {
    const float* item = (const float*)d_in[0];
    const float* attr = (const float*)d_in[1];
    const float* cw   = (const float*)d_in[2];
    const float* bfil = (const float*)d_in[3];
    const float* bbia = (const float*)d_in[4];
    const float* w1   = (const float*)d_in[5];
    const float* b1   = (const float*)d_in[6];
    const float* w2   = (const float*)d_in[7];
    const float* b2   = (const float*)d_in[8];
    const float* gam  = (const float*)d_in[9];
    const float* bet  = (const float*)d_in[10];
    float* out = (float*)d_out;

    cudaFuncSetAttribute(k_main, cudaFuncAttributeMaxDynamicSharedMemorySize,
                         SMEM_FLOATS * (int)sizeof(float));

    k_pre<<<BB / 8, 256>>>(attr, w1, b1, w2, b2, bfil, bbia);
    k_main<<<BB, 256, SMEM_FLOATS * (int)sizeof(float)>>>(item, cw, gam, bet, out);
}

// round 3
// speedup vs baseline: 1.5720x; 1.1917x over previous
#include <cuda_runtime.h>
#include <cstdint>
#include <math.h>

#define BB   4096
#define SS   50
#define HIDD 256
#define NHH  4
#define HDD  64
#define FBB  26
#define PPER 208   // NH*FB*2

typedef unsigned long long u64;

// ---------------- scratch ----------------
__device__ __align__(16) float g_fb[BB * PPER];

// ---------------- packed f32x2 helpers ----------------
__device__ __forceinline__ void ffma2(u64 &d, u64 a, u64 b) {
    asm("fma.rn.f32x2 %0, %1, %2, %0;" : "+l"(d) : "l"(a), "l"(b));
}
__device__ __forceinline__ u64 pack2(float lo, float hi) {
    u64 r; asm("mov.b64 %0, {%1, %2};" : "=l"(r) : "f"(lo), "f"(hi)); return r;
}
__device__ __forceinline__ void unpack2(u64 v, float &lo, float &hi) {
    asm("mov.b64 {%0, %1}, %2;" : "=f"(lo), "=f"(hi) : "l"(v));
}

// ---------------- fused prologue (unchanged from R2) ----------------
__global__ __launch_bounds__(256) void k_pre(const float* __restrict__ attr,
                                             const float* __restrict__ w1,
                                             const float* __restrict__ b1,
                                             const float* __restrict__ w2,
                                             const float* __restrict__ b2,
                                             const float* __restrict__ bfil,
                                             const float* __restrict__ bbia) {
    __shared__ float cs[8 * HIDD];
    __shared__ float hs[8 * HIDD];
    int b0  = blockIdx.x * 8;
    int tid = threadIdx.x;

    {   // ctx mean
        int c4 = tid & 63;
        int mg = tid >> 6;
        #pragma unroll
        for (int mo = 0; mo < 2; mo++) {
            int m = mg + mo * 4;
            const float4* p = reinterpret_cast<const float4*>(
                attr + (size_t)(b0 + m) * SS * HIDD) + c4;
            float sx = 0.f, sy = 0.f, sz = 0.f, sw = 0.f;
            #pragma unroll
            for (int t = 0; t < SS; t++) {
                float4 v = p[(size_t)t * (HIDD / 4)];
                sx += v.x; sy += v.y; sz += v.z; sw += v.w;
            }
            float4 o; o.x = sx * 0.02f; o.y = sy * 0.02f; o.z = sz * 0.02f; o.w = sw * 0.02f;
            reinterpret_cast<float4*>(cs)[m * (HIDD / 4) + c4] = o;
        }
    }
    __syncthreads();

    {   // gelu MLP
        float acc[8];
        float bv = b1[tid];
        #pragma unroll
        for (int m = 0; m < 8; m++) acc[m] = bv;
        for (int k4 = 0; k4 < HIDD / 4; k4++) {
            int k = 4 * k4;
            float wa = w1[(k + 0) * HIDD + tid];
            float wb = w1[(k + 1) * HIDD + tid];
            float wc = w1[(k + 2) * HIDD + tid];
            float wd = w1[(k + 3) * HIDD + tid];
            #pragma unroll
            for (int m = 0; m < 8; m++) {
                float4 c4 = *reinterpret_cast<const float4*>(&cs[m * HIDD + k]);
                acc[m] += c4.x * wa + c4.y * wb + c4.z * wc + c4.w * wd;
            }
        }
        #pragma unroll
        for (int m = 0; m < 8; m++) {
            float x = acc[m];
            hs[m * HIDD + tid] = 0.5f * x * (1.0f + erff(x * 0.70710678118654752f));
        }
    }
    __syncthreads();

    if (tid < PPER) {   // adapt + fold
        float acc[8];
        float bv = b2[tid];
        #pragma unroll
        for (int m = 0; m < 8; m++) acc[m] = bv;
        for (int k4 = 0; k4 < HIDD / 4; k4++) {
            int k = 4 * k4;
            float wa = w2[(k + 0) * PPER + tid];
            float wb = w2[(k + 1) * PPER + tid];
            float wc = w2[(k + 2) * PPER + tid];
            float wd = w2[(k + 3) * PPER + tid];
            #pragma unroll
            for (int m = 0; m < 8; m++) {
                float4 h4 = *reinterpret_cast<const float4*>(&hs[m * HIDD + k]);
                acc[m] += h4.x * wa + h4.y * wb + h4.z * wc + h4.w * wd;
            }
        }
        int h = tid / 52;
        int r = tid % 52;
        int fi = r >> 1;
        bool isScale = (r & 1) == 0;
        float basef = bfil[h * FBB + fi];
        float baseb = bbia[h * FBB + fi];
        #pragma unroll
        for (int m = 0; m < 8; m++) {
            float v = isScale ? basef * (1.0f + acc[m]) : (baseb + acc[m]);
            g_fb[(b0 + m) * PPER + tid] = v;
        }
    }
}

// ---------------- k_main helpers (templated on row range + s-parity) ----------
// acc[i] holds output row t = 2*(I0+i)+p for the thread's column pair d0.
// s-loop index s = 2e+PAR+p, coefficient distance (t-s) = 2*(I0+i)-(2e+PAR),
// compile-time static. Circulant kernel is even-symmetric: c[d] = c[50-d].

template<int I0, int NI, int PAR>
__device__ __forceinline__ void conv_pass(u64* acc, const float* xcol,
                                          const u64* cdh, int p) {
    u64 cc[13];
    #pragma unroll
    for (int j = 0; j < 13; j++) cc[j] = cdh[2 * j + PAR];
    #pragma unroll
    for (int e = 0; e < 25; e++) {
        int srow = 2 * e + PAR + p;
        if (2 * e + PAR + 1 >= 50) { if (srow >= 50) srow -= 50; }
        u64 xv = *reinterpret_cast<const u64*>(xcol + srow * HIDD);
        #pragma unroll
        for (int i = 0; i < NI; i++) {
            const int dd = ((2 * (I0 + i) - (2 * e + PAR)) % 50 + 50) % 50;
            const int f  = (dd <= 25) ? dd : (50 - dd);
            ffma2(acc[i], xv, cc[f >> 1]);
        }
    }
}

template<int I0, int NI>
__device__ __forceinline__ void acc_init(u64* acc, const float* bvs, int h, int p) {
    #pragma unroll
    for (int i = 0; i < NI; i++) {
        float bv = bvs[h * 50 + 2 * (I0 + i) + p];
        acc[i] = pack2(bv, bv);
    }
}

template<int I0, int NI>
__device__ __forceinline__ void wavelet_combine(u64* acc, const float* xs,
                                                const float* __restrict__ cw,
                                                int h, int d0, int p) {
    float sgn = p ? -1.0f : 1.0f;
    int dl = d0 & 63;
    #pragma unroll
    for (int i = 0; i < NI; i++) {
        int ia = I0 + i;
        float2 e = *reinterpret_cast<const float2*>(&xs[(2 * ia)     * HIDD + d0]);
        float2 o = *reinterpret_cast<const float2*>(&xs[(2 * ia + 1) * HIDD + d0]);
        float2 w = __ldg(reinterpret_cast<const float2*>(cw + h * (25 * HDD) + ia * HDD + dl));
        float ax = 0.5f * (e.x + o.x), ay = 0.5f * (e.y + o.y);
        float dx = 0.5f * (e.x - o.x) * w.x, dy = 0.5f * (e.y - o.y) * w.y;
        float wx = ax + sgn * dx, wy = ay + sgn * dy;
        float ix = p ? o.x : e.x;
        float iy = p ? o.y : e.y;
        float fx, fy; unpack2(acc[i], fx, fy);
        acc[i] = pack2(0.7f * wx + 0.3f * fx + ix,
                       0.7f * wy + 0.3f * fy + iy);
    }
}

template<int I0, int NI>
__device__ __forceinline__ void store_rows(const u64* acc, float* xs, int d0, int p) {
    #pragma unroll
    for (int i = 0; i < NI; i++)
        *reinterpret_cast<u64*>(&xs[(2 * (I0 + i) + p) * HIDD + d0]) = acc[i];
}

// ---------------- K4: 512 threads, 2 CTAs/SM ----------------
// smem float offsets: xs 0:12800 | cd 12800:208 | bvs 13008:200 | fbs 13208:208
//                     ctab 13416:50 | gs 13466:256 | bsv 13722:256  => 13978 floats
#define SMEM_FLOATS 13978

__global__ __launch_bounds__(512, 2) void k_main(const float* __restrict__ item,
                                                 const float* __restrict__ cw,
                                                 const float* __restrict__ gamma,
                                                 const float* __restrict__ beta,
                                                 float* __restrict__ out) {
    extern __shared__ float sm[];
    float* xs   = sm;
    float* cd   = sm + 12800;
    float* bvs  = sm + 13008;
    float* fbs  = sm + 13208;
    float* ctab = sm + 13416;
    float* gs   = sm + 13466;
    float* bsv  = sm + 13722;

    int b   = blockIdx.x;
    int tid = threadIdx.x;
    const float* itemb = item + (size_t)b * SS * HIDD;

    // ---- stage ----
    for (int i = tid; i < SS * HIDD / 4; i += 512)
        reinterpret_cast<float4*>(xs)[i] = reinterpret_cast<const float4*>(itemb)[i];
    if (tid < PPER) fbs[tid] = g_fb[b * PPER + tid];
    if (tid < 50)   ctab[tid] = cospif((float)tid * (1.0f / 25.0f));
    if (tid < HIDD) { gs[tid] = gamma[tid]; bsv[tid] = beta[tid]; }
    __syncthreads();

    // ---- circulant coeffs (even-symmetric, m=0..25, duplicated f32x2) + bias ----
    if (tid < 104) {
        int h = tid / 26, m = tid % 26;
        const float* fh = fbs + h * 52;
        float cacc = 0.f;
        int idx = 0;
        #pragma unroll
        for (int k = 0; k < 26; k++) {
            float w = (k == 0 || k == 25) ? 1.0f : 2.0f;
            cacc += fh[2 * k] * w * ctab[idx];
            idx += m; if (idx >= 50) idx -= 50;
        }
        reinterpret_cast<float2*>(cd)[h * 26 + m] = make_float2(cacc * 0.02f, cacc * 0.02f);
    }
    if (tid < 200) {
        int h = tid / 50, m = tid % 50;
        const float* fh = fbs + h * 52;
        float bacc = 0.f;
        int idx = 0;
        #pragma unroll
        for (int k = 0; k < 26; k++) {
            float w = (k == 0 || k == 25) ? 1.0f : 2.0f;
            bacc += fh[2 * k + 1] * w * ctab[idx];
            idx += m; if (idx >= 50) idx -= 50;
        }
        bvs[h * 50 + m] = bacc * 0.14142135623730951f;
    }
    __syncthreads();

    // ---- thread mapping: tid = rh*256 + p*128 + dp ----
    int dp = tid & 127;
    int p  = (tid >> 7) & 1;
    int rh = tid >> 8;            // warp-uniform
    int d0 = dp * 2;
    int h  = dp >> 5;

    const u64*   cdh  = reinterpret_cast<const u64*>(cd) + h * 26;
    const float* xcol = xs + d0;

    u64 acc[13];
    if (rh == 0) {
        acc_init<0, 13>(acc, bvs, h, p);
        conv_pass<0, 13, 0>(acc, xcol, cdh, p);
    } else {
        acc_init<13, 12>(acc, bvs, h, p);
        conv_pass<13, 12, 0>(acc, xcol, cdh, p);
    }
    __syncthreads();   // uniform; scheduling fence between coefficient banks
    if (rh == 0) conv_pass<0, 13, 1>(acc, xcol, cdh, p);
    else         conv_pass<13, 12, 1>(acc, xcol, cdh, p);

    // ---- wavelet + combine + residual (reads xs; no writes yet) ----
    if (rh == 0) wavelet_combine<0, 13>(acc, xs, cw, h, d0, p);
    else         wavelet_combine<13, 12>(acc, xs, cw, h, d0, p);

    __syncthreads();   // all reads of xs done
    if (rh == 0) store_rows<0, 13>(acc, xs, d0, p);
    else         store_rows<13, 12>(acc, xs, d0, p);
    __syncthreads();

    // ---- LayerNorm: 16 warps over 50 rows ----
    int wid = tid >> 5, lane = tid & 31;
    float* outb = out + (size_t)b * SS * HIDD;
    for (int t = wid; t < SS; t += 16) {
        float v[8];
        float s1 = 0.f, s2 = 0.f;
        #pragma unroll
        for (int q = 0; q < 8; q++) {
            v[q] = xs[t * HIDD + lane + 32 * q];
            s1 += v[q]; s2 += v[q] * v[q];
        }
        #pragma unroll
        for (int off = 16; off; off >>= 1) {
            s1 += __shfl_xor_sync(0xffffffffu, s1, off);
            s2 += __shfl_xor_sync(0xffffffffu, s2, off);
        }
        float mu  = s1 * (1.0f / 256.0f);
        float var = s2 * (1.0f / 256.0f) - mu * mu;
        float rs  = rsqrtf(var + 1e-12f);
        #pragma unroll
        for (int q = 0; q < 8; q++) {
            int c = lane + 32 * q;
            outb[t * HIDD + c] = (v[q] - mu) * rs * gs[c] + bsv[c];
        }
    }
}

// ---------------- launcher ----------------
extern "C" void kernel_launch(void* const* d_in, const int* in_sizes, int n_in,
                              void* d_out, int out_size) {
    const float* item = (const float*)d_in[0];
    const float* attr = (const float*)d_in[1];
    const float* cw   = (const float*)d_in[2];
    const float* bfil = (const float*)d_in[3];
    const float* bbia = (const float*)d_in[4];
    const float* w1   = (const float*)d_in[5];
    const float* b1   = (const float*)d_in[6];
    const float* w2   = (const float*)d_in[7];
    const float* b2   = (const float*)d_in[8];
    const float* gam  = (const float*)d_in[9];
    const float* bet  = (const float*)d_in[10];
    float* out = (float*)d_out;

    cudaFuncSetAttribute(k_main, cudaFuncAttributeMaxDynamicSharedMemorySize,
                         SMEM_FLOATS * (int)sizeof(float));

    k_pre<<<BB / 8, 256>>>(attr, w1, b1, w2, b2, bfil, bbia);
    k_main<<<BB, 512, SMEM_FLOATS * (int)sizeof(float)>>>(item, cw, gam, bet, out);
}